// round 13
// baseline (speedup 1.0000x reference)
#include <cuda_runtime.h>
#include <cuda_fp16.h>
#include <cstdint>

// VQ via legacy mma.sync fp16-split GEMM (sm_103-safe).
// R13: fp16 3-pass (R12-validated numerics) + TILE_M=256 (2 m16 tiles/warp)
// which fits the 2-CTA/SM register budget only because fp16 A-frags are half
// the size of tf32. Each B fragment feeds 6 MMAs.

#define D        64
#define K        512
#define TILE_M   256
#define THREADS  256
#define ASTRIDE  36      // u32 stride per A row (32 u32 payload + 4 pad)

typedef unsigned long long u64;
typedef unsigned int       u32;

// ---------------- device scratch ----------------
__device__ float g_embT[K * D];        // [512][64] codebook rows fp32
__device__ uint4 g_Bfrag[64 * 4 * 32]; // fp16 fragment B: [c][ks][lane] = (bh0,bh1,bl0,bl1)
__device__ float g_en2[K];
__device__ float g_err_sum;
__device__ u32   g_done;

__device__ __forceinline__ u32 smem_u32(const void* p) {
    u32 a;
    asm("{ .reg .u64 t; cvta.to.shared.u64 t, %1; cvt.u32.u64 %0, t; }" : "=r"(a) : "l"(p));
    return a;
}
__device__ __forceinline__ u32 pack_h2(float lo, float hi) {
    __half2 h = __halves2half2(__float2half_rn(lo), __float2half_rn(hi));
    return *(u32*)&h;
}
__device__ __forceinline__ u32 h2_split_hi(float a, float b) {
    return pack_h2(a, b);
}
__device__ __forceinline__ u32 h2_split_lo(float a, float b) {
    float ra = __fsub_rn(a, __half2float(__float2half_rn(a)));
    float rb = __fsub_rn(b, __half2float(__float2half_rn(b)));
    return pack_h2(ra, rb);
}

#define MMA_F16(c0, c1, c2, c3, a0, a1, a2, a3, b0, b1)                      \
    asm volatile("mma.sync.aligned.m16n8k16.row.col.f32.f16.f16.f32 "       \
                 "{%0,%1,%2,%3}, {%4,%5,%6,%7}, {%8,%9}, {%0,%1,%2,%3};"    \
                 : "+f"(c0), "+f"(c1), "+f"(c2), "+f"(c3)                   \
                 : "r"(a0), "r"(a1), "r"(a2), "r"(a3), "r"(b0), "r"(b1))

#define CP16(dst, src) \
    asm volatile("cp.async.cg.shared.global [%0], [%1], 16;" :: "r"(dst), "l"(src))
#define CP_COMMIT() asm volatile("cp.async.commit_group;" ::: "memory")
#define CP_WAIT0()  asm volatile("cp.async.wait_group 0;" ::: "memory")

// ---------------- precompute ----------------
__global__ void vq_pre(const float* __restrict__ emb) {
    int gt = blockIdx.x * blockDim.x + threadIdx.x;
    int stride = gridDim.x * blockDim.x;
    if (gt == 0) { g_err_sum = 0.0f; g_done = 0u; }
    for (int i = gt; i < K * D; i += stride) {
        int k = i >> 6, d = i & 63;
        g_embT[i] = emb[d * K + k];
    }
    for (int k = gt; k < K; k += stride) {
        float s = 0.0f;
        for (int d = 0; d < D; d++) {
            float v = emb[d * K + k];
            s = __fadd_rn(s, __fmul_rn(v, v));
        }
        g_en2[k] = s;
    }
    // fp16 fragment-ordered B: idx -> [c][ks][lane]
    for (int idx = gt; idx < 64 * 4 * 32; idx += stride) {
        int c  = idx >> 7;
        int ks = (idx >> 5) & 3;
        int l  = idx & 31;
        int g = l >> 2, t = l & 3;
        int n = c * 8 + g;
        int k0 = 16 * ks + 2 * t;
        float v00 = emb[(k0    ) * K + n], v01 = emb[(k0 + 1) * K + n];
        float v10 = emb[(k0 + 8) * K + n], v11 = emb[(k0 + 9) * K + n];
        uint4 w;
        w.x = h2_split_hi(v00, v01);
        w.y = h2_split_hi(v10, v11);
        w.z = h2_split_lo(v00, v01);
        w.w = h2_split_lo(v10, v11);
        g_Bfrag[idx] = w;
    }
}

// ---------------- smem layout (float indices) ----------------
// work = max(A staging 2*256*36 u32 = 18432 floats, B dbl 2*1024 uint4 = 8192)
#define SM_WORK  0
#define SM_EN2   18432
#define SM_F     (SM_EN2 + K)             // 18944 (256 floats)
#define SM_RED   (SM_F + TILE_M)          // 19200 (256 floats)
#define SM_PM    (SM_RED + THREADS)       // 19456 (256 u64 = 512 floats)
#define SMEM_FLOATS (SM_PM + 2 * TILE_M)  // 19968
#define SMEM_SZ  (SMEM_FLOATS * 4)        // 79872 B

__global__ __launch_bounds__(THREADS, 2)
void vq_main(const float* __restrict__ x, float* __restrict__ out,
             int n_x, int loss_idx, int nblocks) {
    extern __shared__ float smem[];
    float* work = smem + SM_WORK;
    float* en2s = smem + SM_EN2;
    float* Fs   = smem + SM_F;
    float* red  = smem + SM_RED;
    u64*   pm   = (u64*)(smem + SM_PM);

    const int tid = threadIdx.x;
    const int wid = tid >> 5, lid = tid & 31;
    const int g = lid >> 2, t = lid & 3;
    const long mbase = (long)blockIdx.x * TILE_M;

    for (int i = tid; i < K; i += THREADS) en2s[i] = g_en2[i];

    // ---- stage A tile (256 rows): packed fp16 hi/lo planes ----
    u32* Ahi32 = (u32*)work;
    u32* Alo32 = Ahi32 + TILE_M * ASTRIDE;
    {
        const float4* xg = (const float4*)(x + mbase * D);
        #pragma unroll
        for (int i = tid; i < TILE_M * D / 4; i += THREADS) {
            int row = i >> 4, q = i & 15;
            float4 v = xg[i];
            int o = row * ASTRIDE + q * 2;
            Ahi32[o]     = h2_split_hi(v.x, v.y);
            Ahi32[o + 1] = h2_split_hi(v.z, v.w);
            Alo32[o]     = h2_split_lo(v.x, v.y);
            Alo32[o + 1] = h2_split_lo(v.z, v.w);
        }
    }
    // F per row (one row per thread, reference sequential order)
    {
        const float4* xr = (const float4*)(x + (mbase + tid) * D);
        float F = 0.0f;
        #pragma unroll
        for (int i = 0; i < D / 4; i++) {
            float4 v = xr[i];
            F = __fadd_rn(F, __fmul_rn(v.x, v.x));
            F = __fadd_rn(F, __fmul_rn(v.y, v.y));
            F = __fadd_rn(F, __fmul_rn(v.z, v.z));
            F = __fadd_rn(F, __fmul_rn(v.w, v.w));
        }
        Fs[tid] = F;
    }
    __syncthreads();

    // ---- A fragments for two m16 tiles (rows wid*32 .. wid*32+31) ----
    const int rbase = wid * 32;
    u32 ah0[4][4], al0[4][4], ah1[4][4], al1[4][4];
    {
        const int r0 = (rbase + g) * ASTRIDE,      r1 = (rbase + g + 8) * ASTRIDE;
        const int r2 = (rbase + 16 + g) * ASTRIDE, r3 = (rbase + 24 + g) * ASTRIDE;
        #pragma unroll
        for (int ks = 0; ks < 4; ks++) {
            int c = 8 * ks + t;
            ah0[ks][0] = Ahi32[r0 + c];
            ah0[ks][1] = Ahi32[r1 + c];
            ah0[ks][2] = Ahi32[r0 + c + 4];
            ah0[ks][3] = Ahi32[r1 + c + 4];
            al0[ks][0] = Alo32[r0 + c];
            al0[ks][1] = Alo32[r1 + c];
            al0[ks][2] = Alo32[r0 + c + 4];
            al0[ks][3] = Alo32[r1 + c + 4];
            ah1[ks][0] = Ahi32[r2 + c];
            ah1[ks][1] = Ahi32[r3 + c];
            ah1[ks][2] = Ahi32[r2 + c + 4];
            ah1[ks][3] = Ahi32[r3 + c + 4];
            al1[ks][0] = Alo32[r2 + c];
            al1[ks][1] = Alo32[r3 + c];
            al1[ks][2] = Alo32[r2 + c + 4];
            al1[ks][3] = Alo32[r3 + c + 4];
        }
    }
    const float F0 = Fs[rbase + g],      F1 = Fs[rbase + g + 8];
    const float F2 = Fs[rbase + 16 + g], F3 = Fs[rbase + 24 + g];
    __syncthreads();   // A reads done; work region becomes B double buffer

    uint4* Bbuf = (uint4*)work;            // 2 x 1024 uint4 (2 x 16 KB)
    const u32 sbB = smem_u32(Bbuf);

    // prologue: chunk 0 (64 codes) -> buf 0
    {
        const uint4* src = g_Bfrag;
        #pragma unroll
        for (int i = tid; i < 1024; i += THREADS)
            CP16(sbB + i * 16, src + i);
        CP_COMMIT();
    }

    u64 pb0 = ~0ULL, pb1 = ~0ULL, pb2 = ~0ULL, pb3 = ~0ULL;

    for (int e = 0; e < 8; e++) {
        CP_WAIT0();
        __syncthreads();        // buf[e&1] full; all warps done with chunk e-1

        if (e < 7) {
            const uint4* src = g_Bfrag + (e + 1) * 1024;
            const u32 dst = sbB + ((e + 1) & 1) * 16384;
            #pragma unroll
            for (int i = tid; i < 1024; i += THREADS)
                CP16(dst + i * 16, src + i);
            CP_COMMIT();
        }

        const uint4* Bs = Bbuf + (e & 1) * 1024;
        for (int cc = 0; cc < 8; cc++) {
            const uint4* bb = Bs + cc * 128 + lid;
            float A0=0,A1=0,A2=0,A3=0, X0=0,X1=0,X2=0,X3=0;   // tile0 hh / merged
            float C0=0,C1=0,C2=0,C3=0, Y0=0,Y1=0,Y2=0,Y3=0;   // tile1 hh / merged
            #pragma unroll
            for (int ks = 0; ks < 4; ks++) {
                uint4 b = bb[ks * 32];   // LDS.128, conflict-free; feeds 6 MMAs
                MMA_F16(A0,A1,A2,A3, ah0[ks][0],ah0[ks][1],ah0[ks][2],ah0[ks][3], b.x, b.y);
                MMA_F16(C0,C1,C2,C3, ah1[ks][0],ah1[ks][1],ah1[ks][2],ah1[ks][3], b.x, b.y);
                MMA_F16(X0,X1,X2,X3, ah0[ks][0],ah0[ks][1],ah0[ks][2],ah0[ks][3], b.z, b.w);
                MMA_F16(Y0,Y1,Y2,Y3, ah1[ks][0],ah1[ks][1],ah1[ks][2],ah1[ks][3], b.z, b.w);
                MMA_F16(X0,X1,X2,X3, al0[ks][0],al0[ks][1],al0[ks][2],al0[ks][3], b.x, b.y);
                MMA_F16(Y0,Y1,Y2,Y3, al1[ks][0],al1[ks][1],al1[ks][2],al1[ks][3], b.x, b.y);
            }
            const int cbase = (e * 8 + cc) * 8 + 2 * t;
            float2 e2 = *(float2*)(en2s + cbase);
            float s;
            u64 p;
            s = __fadd_rn(A0, X0);
            p = ((u64)__float_as_uint(fmaf(-2.0f, s, __fadd_rn(F0, e2.x))) << 9) | (u32)cbase;
            if (p < pb0) pb0 = p;
            s = __fadd_rn(A1, X1);
            p = ((u64)__float_as_uint(fmaf(-2.0f, s, __fadd_rn(F0, e2.y))) << 9) | (u32)(cbase + 1);
            if (p < pb0) pb0 = p;
            s = __fadd_rn(A2, X2);
            p = ((u64)__float_as_uint(fmaf(-2.0f, s, __fadd_rn(F1, e2.x))) << 9) | (u32)cbase;
            if (p < pb1) pb1 = p;
            s = __fadd_rn(A3, X3);
            p = ((u64)__float_as_uint(fmaf(-2.0f, s, __fadd_rn(F1, e2.y))) << 9) | (u32)(cbase + 1);
            if (p < pb1) pb1 = p;
            s = __fadd_rn(C0, Y0);
            p = ((u64)__float_as_uint(fmaf(-2.0f, s, __fadd_rn(F2, e2.x))) << 9) | (u32)cbase;
            if (p < pb2) pb2 = p;
            s = __fadd_rn(C1, Y1);
            p = ((u64)__float_as_uint(fmaf(-2.0f, s, __fadd_rn(F2, e2.y))) << 9) | (u32)(cbase + 1);
            if (p < pb2) pb2 = p;
            s = __fadd_rn(C2, Y2);
            p = ((u64)__float_as_uint(fmaf(-2.0f, s, __fadd_rn(F3, e2.x))) << 9) | (u32)cbase;
            if (p < pb3) pb3 = p;
            s = __fadd_rn(C3, Y3);
            p = ((u64)__float_as_uint(fmaf(-2.0f, s, __fadd_rn(F3, e2.y))) << 9) | (u32)(cbase + 1);
            if (p < pb3) pb3 = p;
        }
        // no trailing sync: next iteration's leading sync is the read-done barrier
    }

    // ---- reduce best across the 4 threads of each mma group ----
    #pragma unroll
    for (int off = 1; off < 4; off <<= 1) {
        u64 q0 = __shfl_xor_sync(0xffffffffu, pb0, off);
        u64 q1 = __shfl_xor_sync(0xffffffffu, pb1, off);
        u64 q2 = __shfl_xor_sync(0xffffffffu, pb2, off);
        u64 q3 = __shfl_xor_sync(0xffffffffu, pb3, off);
        if (q0 < pb0) pb0 = q0;
        if (q1 < pb1) pb1 = q1;
        if (q2 < pb2) pb2 = q2;
        if (q3 < pb3) pb3 = q3;
    }
    __syncthreads();
    if (t == 0) {
        pm[rbase + g]      = pb0;
        pm[rbase + g + 8]  = pb1;
        pm[rbase + 16 + g] = pb2;
        pm[rbase + 24 + g] = pb3;
    }
    __syncthreads();

    // ---- gather winning code row, error, store (all 256 threads) ----
    float err = 0.0f;
    {
        int kst = (int)(pm[tid] & 511ULL);
        const float4* qr = (const float4*)(g_embT + kst * D);
        const float4* xr = (const float4*)(x + (mbase + tid) * D);
        float4* og = (float4*)(out + (mbase + tid) * D);
        #pragma unroll
        for (int i = 0; i < D / 4; i++) {
            float4 qv = qr[i], v = xr[i];
            float u0 = v.x - qv.x, u1 = v.y - qv.y, u2 = v.z - qv.z, u3 = v.w - qv.w;
            err = fmaf(u0, u0, err); err = fmaf(u1, u1, err);
            err = fmaf(u2, u2, err); err = fmaf(u3, u3, err);
            og[i] = qv;
        }
    }

    // ---- loss reduce + last-block finalize ----
    red[tid] = err;
    __syncthreads();
    #pragma unroll
    for (int s = THREADS / 2; s > 0; s >>= 1) {
        if (tid < s) red[tid] += red[tid + s];
        __syncthreads();
    }
    if (tid == 0) {
        atomicAdd(&g_err_sum, red[0]);
        __threadfence();
        u32 done = atomicAdd(&g_done, 1u);
        if (done == (u32)(nblocks - 1)) {
            __threadfence();
            out[loss_idx] = 1.25f * g_err_sum / (float)n_x;
        }
    }
}

extern "C" void kernel_launch(void* const* d_in, const int* in_sizes, int n_in,
                              void* d_out, int out_size) {
    const float* x   = (const float*)d_in[0];
    const float* emb = (const float*)d_in[1];
    float* out = (float*)d_out;

    const int n_x  = in_sizes[0];            // 8388608
    const int grid = n_x / D / TILE_M;       // 512

    cudaFuncSetAttribute(vq_main, cudaFuncAttributeMaxDynamicSharedMemorySize, SMEM_SZ);

    vq_pre<<<64, 256>>>(emb);
    vq_main<<<grid, THREADS, SMEM_SZ>>>(x, out, n_x, out_size - 1, grid);
}

// round 14
// speedup vs baseline: 1.6518x; 1.6518x over previous
#include <cuda_runtime.h>
#include <cuda_fp16.h>
#include <cstdint>

// VQ via legacy mma.sync fp16-split GEMM (sm_103-safe).
// R14: R12 numerics/shape (TILE_M=128, fp16 3-pass, 2 CTAs/SM) with TWO
// n-chunks per mainloop iteration -> 4 independent MMA chains (max depth 8),
// register slack for B-fragment hoisting, epilogue overlapped with MMAs.

#define D        64
#define K        512
#define TILE_M   128
#define THREADS  256
#define ASTRIDE  36      // u32 stride per A row (32 u32 payload + 4 pad)

typedef unsigned long long u64;
typedef unsigned int       u32;

// ---------------- device scratch ----------------
__device__ float g_embT[K * D];        // [512][64] codebook rows fp32
__device__ uint4 g_Bfrag[64 * 4 * 32]; // fp16 fragment B: [c][ks][lane] = (bh0,bh1,bl0,bl1)
__device__ float g_en2[K];
__device__ float g_err_sum;
__device__ u32   g_done;

__device__ __forceinline__ u32 smem_u32(const void* p) {
    u32 a;
    asm("{ .reg .u64 t; cvta.to.shared.u64 t, %1; cvt.u32.u64 %0, t; }" : "=r"(a) : "l"(p));
    return a;
}
__device__ __forceinline__ u32 pack_h2(float lo, float hi) {
    __half2 h = __halves2half2(__float2half_rn(lo), __float2half_rn(hi));
    return *(u32*)&h;
}
__device__ __forceinline__ u32 h2_split_hi(float a, float b) {
    return pack_h2(a, b);
}
__device__ __forceinline__ u32 h2_split_lo(float a, float b) {
    float ra = __fsub_rn(a, __half2float(__float2half_rn(a)));
    float rb = __fsub_rn(b, __half2float(__float2half_rn(b)));
    return pack_h2(ra, rb);
}

#define MMA_F16(c0, c1, c2, c3, a0, a1, a2, a3, b0, b1)                      \
    asm volatile("mma.sync.aligned.m16n8k16.row.col.f32.f16.f16.f32 "       \
                 "{%0,%1,%2,%3}, {%4,%5,%6,%7}, {%8,%9}, {%0,%1,%2,%3};"    \
                 : "+f"(c0), "+f"(c1), "+f"(c2), "+f"(c3)                   \
                 : "r"(a0), "r"(a1), "r"(a2), "r"(a3), "r"(b0), "r"(b1))

#define CP16(dst, src) \
    asm volatile("cp.async.cg.shared.global [%0], [%1], 16;" :: "r"(dst), "l"(src))
#define CP_COMMIT() asm volatile("cp.async.commit_group;" ::: "memory")
#define CP_WAIT0()  asm volatile("cp.async.wait_group 0;" ::: "memory")

// ---------------- precompute ----------------
__global__ void vq_pre(const float* __restrict__ emb) {
    int gt = blockIdx.x * blockDim.x + threadIdx.x;
    int stride = gridDim.x * blockDim.x;
    if (gt == 0) { g_err_sum = 0.0f; g_done = 0u; }
    for (int i = gt; i < K * D; i += stride) {
        int k = i >> 6, d = i & 63;
        g_embT[i] = emb[d * K + k];
    }
    for (int k = gt; k < K; k += stride) {
        float s = 0.0f;
        for (int d = 0; d < D; d++) {
            float v = emb[d * K + k];
            s = __fadd_rn(s, __fmul_rn(v, v));
        }
        g_en2[k] = s;
    }
    // fp16 fragment-ordered B: idx -> [c][ks][lane]
    for (int idx = gt; idx < 64 * 4 * 32; idx += stride) {
        int c  = idx >> 7;
        int ks = (idx >> 5) & 3;
        int l  = idx & 31;
        int g = l >> 2, t = l & 3;
        int n = c * 8 + g;
        int k0 = 16 * ks + 2 * t;
        float v00 = emb[(k0    ) * K + n], v01 = emb[(k0 + 1) * K + n];
        float v10 = emb[(k0 + 8) * K + n], v11 = emb[(k0 + 9) * K + n];
        uint4 w;
        w.x = h2_split_hi(v00, v01);
        w.y = h2_split_hi(v10, v11);
        w.z = h2_split_lo(v00, v01);
        w.w = h2_split_lo(v10, v11);
        g_Bfrag[idx] = w;
    }
}

// ---------------- smem layout (float indices) ----------------
// work = max(A staging 2*128*36 u32 = 9216 floats, B dbl 2*1024 uint4 = 8192)
#define SM_WORK  0
#define SM_EN2   9216
#define SM_F     (SM_EN2 + K)             // 9728
#define SM_RED   (SM_F + TILE_M)          // 9856
#define SM_PM    (SM_RED + THREADS)       // 10112 (128 u64)
#define SMEM_FLOATS (SM_PM + 2 * TILE_M)  // 10368
#define SMEM_SZ  (SMEM_FLOATS * 4)        // 41472 B

__global__ __launch_bounds__(THREADS, 2)
void vq_main(const float* __restrict__ x, float* __restrict__ out,
             int n_x, int loss_idx, int nblocks) {
    extern __shared__ float smem[];
    float* work = smem + SM_WORK;
    float* en2s = smem + SM_EN2;
    float* Fs   = smem + SM_F;
    float* red  = smem + SM_RED;
    u64*   pm   = (u64*)(smem + SM_PM);

    const int tid = threadIdx.x;
    const int wid = tid >> 5, lid = tid & 31;
    const int g = lid >> 2, t = lid & 3;
    const long mbase = (long)blockIdx.x * TILE_M;

    for (int i = tid; i < K; i += THREADS) en2s[i] = g_en2[i];

    // ---- stage A tile: packed fp16 hi/lo planes, padded u32 rows ----
    u32* Ahi32 = (u32*)work;
    u32* Alo32 = Ahi32 + TILE_M * ASTRIDE;
    {
        const float4* xg = (const float4*)(x + mbase * D);
        #pragma unroll
        for (int i = tid; i < TILE_M * D / 4; i += THREADS) {
            int row = i >> 4, q = i & 15;
            float4 v = xg[i];
            int o = row * ASTRIDE + q * 2;
            Ahi32[o]     = h2_split_hi(v.x, v.y);
            Ahi32[o + 1] = h2_split_hi(v.z, v.w);
            Alo32[o]     = h2_split_lo(v.x, v.y);
            Alo32[o + 1] = h2_split_lo(v.z, v.w);
        }
    }
    if (tid < TILE_M) {
        const float4* xr = (const float4*)(x + (mbase + tid) * D);
        float F = 0.0f;
        #pragma unroll
        for (int i = 0; i < D / 4; i++) {
            float4 v = xr[i];
            F = __fadd_rn(F, __fmul_rn(v.x, v.x));
            F = __fadd_rn(F, __fmul_rn(v.y, v.y));
            F = __fadd_rn(F, __fmul_rn(v.z, v.z));
            F = __fadd_rn(F, __fmul_rn(v.w, v.w));
        }
        Fs[tid] = F;
    }
    __syncthreads();

    // ---- A fragments (4 ksteps of k16, hi & lo) ----
    const int rbase = wid * 16;
    u32 ah[4][4], al[4][4];
    {
        const int r0 = (rbase + g) * ASTRIDE, r1 = (rbase + g + 8) * ASTRIDE;
        #pragma unroll
        for (int ks = 0; ks < 4; ks++) {
            int c = 8 * ks + t;
            ah[ks][0] = Ahi32[r0 + c];
            ah[ks][1] = Ahi32[r1 + c];
            ah[ks][2] = Ahi32[r0 + c + 4];
            ah[ks][3] = Ahi32[r1 + c + 4];
            al[ks][0] = Alo32[r0 + c];
            al[ks][1] = Alo32[r1 + c];
            al[ks][2] = Alo32[r0 + c + 4];
            al[ks][3] = Alo32[r1 + c + 4];
        }
    }
    const float Fg  = Fs[rbase + g];
    const float Fg8 = Fs[rbase + g + 8];
    __syncthreads();   // A reads done; work region becomes B double buffer

    uint4* Bbuf = (uint4*)work;            // 2 x 1024 uint4 (2 x 16 KB)
    const u32 sbB = smem_u32(Bbuf);

    // prologue: chunk 0 (64 codes) -> buf 0
    {
        const uint4* src = g_Bfrag;
        #pragma unroll
        for (int i = tid; i < 1024; i += THREADS)
            CP16(sbB + i * 16, src + i);
        CP_COMMIT();
    }

    u64 pb0 = ~0ULL, pb1 = ~0ULL;

    for (int e = 0; e < 8; e++) {
        CP_WAIT0();
        __syncthreads();        // buf[e&1] full; all warps done with chunk e-1

        if (e < 7) {
            const uint4* src = g_Bfrag + (e + 1) * 1024;
            const u32 dst = sbB + ((e + 1) & 1) * 16384;
            #pragma unroll
            for (int i = tid; i < 1024; i += THREADS)
                CP16(dst + i * 16, src + i);
            CP_COMMIT();
        }

        const uint4* Bs = Bbuf + (e & 1) * 1024;
        #pragma unroll
        for (int cp = 0; cp < 4; cp++) {   // two n8-chunks per iteration
            const uint4* bbA = Bs + (2 * cp) * 128 + lid;
            const uint4* bbB = bbA + 128;
            float A0=0,A1=0,A2=0,A3=0, X0=0,X1=0,X2=0,X3=0;   // chunk a: hh, merged
            float C0=0,C1=0,C2=0,C3=0, Y0=0,Y1=0,Y2=0,Y3=0;   // chunk b: hh, merged
            #pragma unroll
            for (int ks = 0; ks < 4; ks++) {
                uint4 ba = bbA[ks * 32];   // LDS.128, conflict-free
                uint4 bc = bbB[ks * 32];
                MMA_F16(A0,A1,A2,A3, ah[ks][0],ah[ks][1],ah[ks][2],ah[ks][3], ba.x, ba.y);
                MMA_F16(C0,C1,C2,C3, ah[ks][0],ah[ks][1],ah[ks][2],ah[ks][3], bc.x, bc.y);
                MMA_F16(X0,X1,X2,X3, ah[ks][0],ah[ks][1],ah[ks][2],ah[ks][3], ba.z, ba.w);
                MMA_F16(Y0,Y1,Y2,Y3, ah[ks][0],ah[ks][1],ah[ks][2],ah[ks][3], bc.z, bc.w);
                MMA_F16(X0,X1,X2,X3, al[ks][0],al[ks][1],al[ks][2],al[ks][3], ba.x, ba.y);
                MMA_F16(Y0,Y1,Y2,Y3, al[ks][0],al[ks][1],al[ks][2],al[ks][3], bc.x, bc.y);
            }
            // epilogue chunk a
            {
                const int cbase = (e * 8 + 2 * cp) * 8 + 2 * t;
                float2 e2 = *(float2*)(en2s + cbase);
                float s; u64 p;
                s = __fadd_rn(A0, X0);
                p = ((u64)__float_as_uint(fmaf(-2.0f, s, __fadd_rn(Fg,  e2.x))) << 9) | (u32)cbase;
                if (p < pb0) pb0 = p;
                s = __fadd_rn(A1, X1);
                p = ((u64)__float_as_uint(fmaf(-2.0f, s, __fadd_rn(Fg,  e2.y))) << 9) | (u32)(cbase + 1);
                if (p < pb0) pb0 = p;
                s = __fadd_rn(A2, X2);
                p = ((u64)__float_as_uint(fmaf(-2.0f, s, __fadd_rn(Fg8, e2.x))) << 9) | (u32)cbase;
                if (p < pb1) pb1 = p;
                s = __fadd_rn(A3, X3);
                p = ((u64)__float_as_uint(fmaf(-2.0f, s, __fadd_rn(Fg8, e2.y))) << 9) | (u32)(cbase + 1);
                if (p < pb1) pb1 = p;
            }
            // epilogue chunk b
            {
                const int cbase = (e * 8 + 2 * cp + 1) * 8 + 2 * t;
                float2 e2 = *(float2*)(en2s + cbase);
                float s; u64 p;
                s = __fadd_rn(C0, Y0);
                p = ((u64)__float_as_uint(fmaf(-2.0f, s, __fadd_rn(Fg,  e2.x))) << 9) | (u32)cbase;
                if (p < pb0) pb0 = p;
                s = __fadd_rn(C1, Y1);
                p = ((u64)__float_as_uint(fmaf(-2.0f, s, __fadd_rn(Fg,  e2.y))) << 9) | (u32)(cbase + 1);
                if (p < pb0) pb0 = p;
                s = __fadd_rn(C2, Y2);
                p = ((u64)__float_as_uint(fmaf(-2.0f, s, __fadd_rn(Fg8, e2.x))) << 9) | (u32)cbase;
                if (p < pb1) pb1 = p;
                s = __fadd_rn(C3, Y3);
                p = ((u64)__float_as_uint(fmaf(-2.0f, s, __fadd_rn(Fg8, e2.y))) << 9) | (u32)(cbase + 1);
                if (p < pb1) pb1 = p;
            }
        }
        // no trailing sync: next iteration's leading sync is the read-done barrier
    }

    // ---- reduce best across the 4 threads of each mma group ----
    #pragma unroll
    for (int off = 1; off < 4; off <<= 1) {
        u64 q0 = __shfl_xor_sync(0xffffffffu, pb0, off);
        u64 q1 = __shfl_xor_sync(0xffffffffu, pb1, off);
        if (q0 < pb0) pb0 = q0;
        if (q1 < pb1) pb1 = q1;
    }
    __syncthreads();
    if (t == 0) {
        pm[rbase + g]     = pb0;
        pm[rbase + g + 8] = pb1;
    }
    __syncthreads();

    // ---- gather winning code row, error, store ----
    float err = 0.0f;
    if (tid < TILE_M) {
        int kst = (int)(pm[tid] & 511ULL);
        const float4* qr = (const float4*)(g_embT + kst * D);
        const float4* xr = (const float4*)(x + (mbase + tid) * D);
        float4* og = (float4*)(out + (mbase + tid) * D);
        #pragma unroll
        for (int i = 0; i < D / 4; i++) {
            float4 qv = qr[i], v = xr[i];
            float u0 = v.x - qv.x, u1 = v.y - qv.y, u2 = v.z - qv.z, u3 = v.w - qv.w;
            err = fmaf(u0, u0, err); err = fmaf(u1, u1, err);
            err = fmaf(u2, u2, err); err = fmaf(u3, u3, err);
            og[i] = qv;
        }
    }

    // ---- loss reduce + last-block finalize ----
    red[tid] = err;
    __syncthreads();
    #pragma unroll
    for (int s = THREADS / 2; s > 0; s >>= 1) {
        if (tid < s) red[tid] += red[tid + s];
        __syncthreads();
    }
    if (tid == 0) {
        atomicAdd(&g_err_sum, red[0]);
        __threadfence();
        u32 done = atomicAdd(&g_done, 1u);
        if (done == (u32)(nblocks - 1)) {
            __threadfence();
            out[loss_idx] = 1.25f * g_err_sum / (float)n_x;
        }
    }
}

extern "C" void kernel_launch(void* const* d_in, const int* in_sizes, int n_in,
                              void* d_out, int out_size) {
    const float* x   = (const float*)d_in[0];
    const float* emb = (const float*)d_in[1];
    float* out = (float*)d_out;

    const int n_x  = in_sizes[0];            // 8388608
    const int grid = n_x / D / TILE_M;       // 1024

    cudaFuncSetAttribute(vq_main, cudaFuncAttributeMaxDynamicSharedMemorySize, SMEM_SZ);

    vq_pre<<<64, 256>>>(emb);
    vq_main<<<grid, THREADS, SMEM_SZ>>>(x, out, n_x, out_size - 1, grid);
}

// round 15
// speedup vs baseline: 1.7802x; 1.0777x over previous
#include <cuda_runtime.h>
#include <cuda_fp16.h>
#include <cstdint>

// VQ via legacy mma.sync fp16-split GEMM (sm_103-safe).
// R15: R14 + chain-depth halved (separate hl/lh chains, 6 independent depth-4
// chains per iteration) + slim float-compare argmin epilogue.

#define D        64
#define K        512
#define TILE_M   128
#define THREADS  256
#define ASTRIDE  36      // u32 stride per A row (32 u32 payload + 4 pad)

typedef unsigned long long u64;
typedef unsigned int       u32;

// ---------------- device scratch ----------------
__device__ float g_embT[K * D];        // [512][64] codebook rows fp32
__device__ uint4 g_Bfrag[64 * 4 * 32]; // fp16 fragment B: [c][ks][lane] = (bh0,bh1,bl0,bl1)
__device__ float g_en2[K];
__device__ float g_err_sum;
__device__ u32   g_done;

__device__ __forceinline__ u32 smem_u32(const void* p) {
    u32 a;
    asm("{ .reg .u64 t; cvta.to.shared.u64 t, %1; cvt.u32.u64 %0, t; }" : "=r"(a) : "l"(p));
    return a;
}
__device__ __forceinline__ u32 pack_h2(float lo, float hi) {
    __half2 h = __halves2half2(__float2half_rn(lo), __float2half_rn(hi));
    return *(u32*)&h;
}
__device__ __forceinline__ u32 h2_split_hi(float a, float b) {
    return pack_h2(a, b);
}
__device__ __forceinline__ u32 h2_split_lo(float a, float b) {
    float ra = __fsub_rn(a, __half2float(__float2half_rn(a)));
    float rb = __fsub_rn(b, __half2float(__float2half_rn(b)));
    return pack_h2(ra, rb);
}

#define MMA_F16(c0, c1, c2, c3, a0, a1, a2, a3, b0, b1)                      \
    asm volatile("mma.sync.aligned.m16n8k16.row.col.f32.f16.f16.f32 "       \
                 "{%0,%1,%2,%3}, {%4,%5,%6,%7}, {%8,%9}, {%0,%1,%2,%3};"    \
                 : "+f"(c0), "+f"(c1), "+f"(c2), "+f"(c3)                   \
                 : "r"(a0), "r"(a1), "r"(a2), "r"(a3), "r"(b0), "r"(b1))

#define CP16(dst, src) \
    asm volatile("cp.async.cg.shared.global [%0], [%1], 16;" :: "r"(dst), "l"(src))
#define CP_COMMIT() asm volatile("cp.async.commit_group;" ::: "memory")
#define CP_WAIT0()  asm volatile("cp.async.wait_group 0;" ::: "memory")

// track (dist, idx) with lowest-index tie-break
#define ARGMIN_UPD(best, bi, dist, idx) \
    do { if ((dist) < (best)) { (best) = (dist); (bi) = (idx); } } while (0)

// ---------------- precompute ----------------
__global__ void vq_pre(const float* __restrict__ emb) {
    int gt = blockIdx.x * blockDim.x + threadIdx.x;
    int stride = gridDim.x * blockDim.x;
    if (gt == 0) { g_err_sum = 0.0f; g_done = 0u; }
    for (int i = gt; i < K * D; i += stride) {
        int k = i >> 6, d = i & 63;
        g_embT[i] = emb[d * K + k];
    }
    for (int k = gt; k < K; k += stride) {
        float s = 0.0f;
        for (int d = 0; d < D; d++) {
            float v = emb[d * K + k];
            s = __fadd_rn(s, __fmul_rn(v, v));
        }
        g_en2[k] = s;
    }
    // fp16 fragment-ordered B: idx -> [c][ks][lane]
    for (int idx = gt; idx < 64 * 4 * 32; idx += stride) {
        int c  = idx >> 7;
        int ks = (idx >> 5) & 3;
        int l  = idx & 31;
        int g = l >> 2, t = l & 3;
        int n = c * 8 + g;
        int k0 = 16 * ks + 2 * t;
        float v00 = emb[(k0    ) * K + n], v01 = emb[(k0 + 1) * K + n];
        float v10 = emb[(k0 + 8) * K + n], v11 = emb[(k0 + 9) * K + n];
        uint4 w;
        w.x = h2_split_hi(v00, v01);
        w.y = h2_split_hi(v10, v11);
        w.z = h2_split_lo(v00, v01);
        w.w = h2_split_lo(v10, v11);
        g_Bfrag[idx] = w;
    }
}

// ---------------- smem layout (float indices) ----------------
#define SM_WORK  0
#define SM_EN2   9216
#define SM_F     (SM_EN2 + K)             // 9728
#define SM_RED   (SM_F + TILE_M)          // 9856
#define SM_PM    (SM_RED + THREADS)       // 10112 (128 u64)
#define SMEM_FLOATS (SM_PM + 2 * TILE_M)  // 10368
#define SMEM_SZ  (SMEM_FLOATS * 4)        // 41472 B

__global__ __launch_bounds__(THREADS, 2)
void vq_main(const float* __restrict__ x, float* __restrict__ out,
             int n_x, int loss_idx, int nblocks) {
    extern __shared__ float smem[];
    float* work = smem + SM_WORK;
    float* en2s = smem + SM_EN2;
    float* Fs   = smem + SM_F;
    float* red  = smem + SM_RED;
    u64*   pm   = (u64*)(smem + SM_PM);

    const int tid = threadIdx.x;
    const int wid = tid >> 5, lid = tid & 31;
    const int g = lid >> 2, t = lid & 3;
    const long mbase = (long)blockIdx.x * TILE_M;

    for (int i = tid; i < K; i += THREADS) en2s[i] = g_en2[i];

    // ---- stage A tile: packed fp16 hi/lo planes, padded u32 rows ----
    u32* Ahi32 = (u32*)work;
    u32* Alo32 = Ahi32 + TILE_M * ASTRIDE;
    {
        const float4* xg = (const float4*)(x + mbase * D);
        #pragma unroll
        for (int i = tid; i < TILE_M * D / 4; i += THREADS) {
            int row = i >> 4, q = i & 15;
            float4 v = xg[i];
            int o = row * ASTRIDE + q * 2;
            Ahi32[o]     = h2_split_hi(v.x, v.y);
            Ahi32[o + 1] = h2_split_hi(v.z, v.w);
            Alo32[o]     = h2_split_lo(v.x, v.y);
            Alo32[o + 1] = h2_split_lo(v.z, v.w);
        }
    }
    if (tid < TILE_M) {
        const float4* xr = (const float4*)(x + (mbase + tid) * D);
        float F = 0.0f;
        #pragma unroll
        for (int i = 0; i < D / 4; i++) {
            float4 v = xr[i];
            F = __fadd_rn(F, __fmul_rn(v.x, v.x));
            F = __fadd_rn(F, __fmul_rn(v.y, v.y));
            F = __fadd_rn(F, __fmul_rn(v.z, v.z));
            F = __fadd_rn(F, __fmul_rn(v.w, v.w));
        }
        Fs[tid] = F;
    }
    __syncthreads();

    // ---- A fragments (4 ksteps of k16, hi & lo) ----
    const int rbase = wid * 16;
    u32 ah[4][4], al[4][4];
    {
        const int r0 = (rbase + g) * ASTRIDE, r1 = (rbase + g + 8) * ASTRIDE;
        #pragma unroll
        for (int ks = 0; ks < 4; ks++) {
            int c = 8 * ks + t;
            ah[ks][0] = Ahi32[r0 + c];
            ah[ks][1] = Ahi32[r1 + c];
            ah[ks][2] = Ahi32[r0 + c + 4];
            ah[ks][3] = Ahi32[r1 + c + 4];
            al[ks][0] = Alo32[r0 + c];
            al[ks][1] = Alo32[r1 + c];
            al[ks][2] = Alo32[r0 + c + 4];
            al[ks][3] = Alo32[r1 + c + 4];
        }
    }
    const float Fg  = Fs[rbase + g];
    const float Fg8 = Fs[rbase + g + 8];
    __syncthreads();   // A reads done; work region becomes B double buffer

    uint4* Bbuf = (uint4*)work;            // 2 x 1024 uint4 (2 x 16 KB)
    const u32 sbB = smem_u32(Bbuf);

    // prologue: chunk 0 (64 codes) -> buf 0
    {
        const uint4* src = g_Bfrag;
        #pragma unroll
        for (int i = tid; i < 1024; i += THREADS)
            CP16(sbB + i * 16, src + i);
        CP_COMMIT();
    }

    float best0 = 3.4e38f, best1 = 3.4e38f;
    u32 bi0 = 0, bi1 = 0;

    for (int e = 0; e < 8; e++) {
        CP_WAIT0();
        __syncthreads();        // buf[e&1] full; all warps done with chunk e-1

        if (e < 7) {
            const uint4* src = g_Bfrag + (e + 1) * 1024;
            const u32 dst = sbB + ((e + 1) & 1) * 16384;
            #pragma unroll
            for (int i = tid; i < 1024; i += THREADS)
                CP16(dst + i * 16, src + i);
            CP_COMMIT();
        }

        const uint4* Bs = Bbuf + (e & 1) * 1024;
        #pragma unroll
        for (int cp = 0; cp < 4; cp++) {   // two n8-chunks per iteration
            const uint4* bbA = Bs + (2 * cp) * 128 + lid;
            const uint4* bbB = bbA + 128;
            // 6 independent chains, each depth 4:
            float A0=0,A1=0,A2=0,A3=0, X0=0,X1=0,X2=0,X3=0, W0=0,W1=0,W2=0,W3=0; // chunk a
            float C0=0,C1=0,C2=0,C3=0, Y0=0,Y1=0,Y2=0,Y3=0, V0=0,V1=0,V2=0,V3=0; // chunk b
            #pragma unroll
            for (int ks = 0; ks < 4; ks++) {
                uint4 ba = bbA[ks * 32];   // LDS.128, conflict-free
                uint4 bc = bbB[ks * 32];
                MMA_F16(A0,A1,A2,A3, ah[ks][0],ah[ks][1],ah[ks][2],ah[ks][3], ba.x, ba.y);
                MMA_F16(C0,C1,C2,C3, ah[ks][0],ah[ks][1],ah[ks][2],ah[ks][3], bc.x, bc.y);
                MMA_F16(X0,X1,X2,X3, ah[ks][0],ah[ks][1],ah[ks][2],ah[ks][3], ba.z, ba.w);
                MMA_F16(Y0,Y1,Y2,Y3, ah[ks][0],ah[ks][1],ah[ks][2],ah[ks][3], bc.z, bc.w);
                MMA_F16(W0,W1,W2,W3, al[ks][0],al[ks][1],al[ks][2],al[ks][3], ba.x, ba.y);
                MMA_F16(V0,V1,V2,V3, al[ks][0],al[ks][1],al[ks][2],al[ks][3], bc.x, bc.y);
            }
            // epilogue chunk a
            {
                const int cbase = (e * 8 + 2 * cp) * 8 + 2 * t;
                float2 e2 = *(float2*)(en2s + cbase);
                float s, d;
                s = __fadd_rn(A0, __fadd_rn(X0, W0));
                d = fmaf(-2.0f, s, __fadd_rn(Fg, e2.x));
                ARGMIN_UPD(best0, bi0, d, (u32)cbase);
                s = __fadd_rn(A1, __fadd_rn(X1, W1));
                d = fmaf(-2.0f, s, __fadd_rn(Fg, e2.y));
                ARGMIN_UPD(best0, bi0, d, (u32)(cbase + 1));
                s = __fadd_rn(A2, __fadd_rn(X2, W2));
                d = fmaf(-2.0f, s, __fadd_rn(Fg8, e2.x));
                ARGMIN_UPD(best1, bi1, d, (u32)cbase);
                s = __fadd_rn(A3, __fadd_rn(X3, W3));
                d = fmaf(-2.0f, s, __fadd_rn(Fg8, e2.y));
                ARGMIN_UPD(best1, bi1, d, (u32)(cbase + 1));
            }
            // epilogue chunk b
            {
                const int cbase = (e * 8 + 2 * cp + 1) * 8 + 2 * t;
                float2 e2 = *(float2*)(en2s + cbase);
                float s, d;
                s = __fadd_rn(C0, __fadd_rn(Y0, V0));
                d = fmaf(-2.0f, s, __fadd_rn(Fg, e2.x));
                ARGMIN_UPD(best0, bi0, d, (u32)cbase);
                s = __fadd_rn(C1, __fadd_rn(Y1, V1));
                d = fmaf(-2.0f, s, __fadd_rn(Fg, e2.y));
                ARGMIN_UPD(best0, bi0, d, (u32)(cbase + 1));
                s = __fadd_rn(C2, __fadd_rn(Y2, V2));
                d = fmaf(-2.0f, s, __fadd_rn(Fg8, e2.x));
                ARGMIN_UPD(best1, bi1, d, (u32)cbase);
                s = __fadd_rn(C3, __fadd_rn(Y3, V3));
                d = fmaf(-2.0f, s, __fadd_rn(Fg8, e2.y));
                ARGMIN_UPD(best1, bi1, d, (u32)(cbase + 1));
            }
        }
        // no trailing sync: next iteration's leading sync is the read-done barrier
    }

    // ---- reduce best across the 4 threads of each mma group ----
    // lexicographic (dist, idx): lowest dist, then lowest index
    #pragma unroll
    for (int off = 1; off < 4; off <<= 1) {
        float b0 = __shfl_xor_sync(0xffffffffu, best0, off);
        u32   i0 = __shfl_xor_sync(0xffffffffu, bi0,   off);
        float b1 = __shfl_xor_sync(0xffffffffu, best1, off);
        u32   i1 = __shfl_xor_sync(0xffffffffu, bi1,   off);
        if (b0 < best0 || (b0 == best0 && i0 < bi0)) { best0 = b0; bi0 = i0; }
        if (b1 < best1 || (b1 == best1 && i1 < bi1)) { best1 = b1; bi1 = i1; }
    }
    __syncthreads();
    if (t == 0) {
        pm[rbase + g]     = ((u64)__float_as_uint(best0) << 9) | bi0;
        pm[rbase + g + 8] = ((u64)__float_as_uint(best1) << 9) | bi1;
    }
    __syncthreads();

    // ---- gather winning code row, error, store ----
    float err = 0.0f;
    if (tid < TILE_M) {
        int kst = (int)(pm[tid] & 511ULL);
        const float4* qr = (const float4*)(g_embT + kst * D);
        const float4* xr = (const float4*)(x + (mbase + tid) * D);
        float4* og = (float4*)(out + (mbase + tid) * D);
        #pragma unroll
        for (int i = 0; i < D / 4; i++) {
            float4 qv = qr[i], v = xr[i];
            float u0 = v.x - qv.x, u1 = v.y - qv.y, u2 = v.z - qv.z, u3 = v.w - qv.w;
            err = fmaf(u0, u0, err); err = fmaf(u1, u1, err);
            err = fmaf(u2, u2, err); err = fmaf(u3, u3, err);
            og[i] = qv;
        }
    }

    // ---- loss reduce + last-block finalize ----
    red[tid] = err;
    __syncthreads();
    #pragma unroll
    for (int s = THREADS / 2; s > 0; s >>= 1) {
        if (tid < s) red[tid] += red[tid + s];
        __syncthreads();
    }
    if (tid == 0) {
        atomicAdd(&g_err_sum, red[0]);
        __threadfence();
        u32 done = atomicAdd(&g_done, 1u);
        if (done == (u32)(nblocks - 1)) {
            __threadfence();
            out[loss_idx] = 1.25f * g_err_sum / (float)n_x;
        }
    }
}

extern "C" void kernel_launch(void* const* d_in, const int* in_sizes, int n_in,
                              void* d_out, int out_size) {
    const float* x   = (const float*)d_in[0];
    const float* emb = (const float*)d_in[1];
    float* out = (float*)d_out;

    const int n_x  = in_sizes[0];            // 8388608
    const int grid = n_x / D / TILE_M;       // 1024

    cudaFuncSetAttribute(vq_main, cudaFuncAttributeMaxDynamicSharedMemorySize, SMEM_SZ);

    vq_pre<<<64, 256>>>(emb);
    vq_main<<<grid, THREADS, SMEM_SZ>>>(x, out, n_x, out_size - 1, grid);
}